// round 8
// baseline (speedup 1.0000x reference)
#include <cuda_runtime.h>

#define S_ 160
#define H_ 768

// scratch (device globals — no allocation allowed)
__device__ float g_yrot[S_ * H_];
__device__ float g_L[S_ * H_];
__device__ float g_R[S_ * H_];

typedef unsigned long long u64;

__device__ __forceinline__ void fma2(u64& d, u64 a, u64 b) {
    asm volatile("fma.rn.f32x2 %0, %1, %2, %0;" : "+l"(d) : "l"(a), "l"(b));
}
__device__ __forceinline__ u64 pack2(float x, float y) {
    u64 r; asm("mov.b64 %0, {%1, %2};" : "=l"(r) : "f"(x), "f"(y)); return r;
}
__device__ __forceinline__ float2 unpack2(u64 v) {
    float2 f; asm("mov.b64 {%0, %1}, %2;" : "=f"(f.x), "=f"(f.y) : "l"(v)); return f;
}
__device__ __forceinline__ float sigf(float x) { return 1.0f / (1.0f + __expf(-x)); }

__device__ __forceinline__ float4 reluadd4(float4 a, float4 b) {
    float4 r;
    r.x = fmaxf(a.x + b.x, 0.f);
    r.y = fmaxf(a.y + b.y, 0.f);
    r.z = fmaxf(a.z + b.z, 0.f);
    r.w = fmaxf(a.w + b.w, 0.f);
    return r;
}

// ---------------------------------------------------------------------------
// Kernel A: RoPE.  grid 160, block 384 (one thread per (2k,2k+1) pair)
// ---------------------------------------------------------------------------
__global__ void rope_kernel(const float* __restrict__ y) {
    int s = blockIdx.x;
    int k = threadIdx.x;  // 0..383
    float inv = expf(-(2.0f * (float)k / 768.0f) * 9.210340371976184f);
    float th = (float)s * inv;
    float sn, cs;
    sincosf(th, &sn, &cs);
    float y0 = y[s * H_ + 2 * k];
    float y1 = y[s * H_ + 2 * k + 1];
    g_yrot[s * H_ + 2 * k]     = y0 * cs - y1 * sn;
    g_yrot[s * H_ + 2 * k + 1] = y1 * cs + y0 * sn;
}

// ---------------------------------------------------------------------------
// Kernel B: L = yrot @ Wa^T ; R = yrot @ Wb^T + b1
// GEMM 160 x 1536 x 768.  BM=32, BN=64, BK=16.  grid (5, 24), 256 threads.
// ---------------------------------------------------------------------------
__global__ __launch_bounds__(256) void lr_kernel(const float* __restrict__ W1,
                                                 const float* __restrict__ b1) {
    __shared__ float As[16][34];    // [k][s-row], padded
    __shared__ float Bs[16][68];    // [k][n], padded

    int t = threadIdx.x;
    int Mtile = blockIdx.x;          // 0..4
    int nbase = blockIdx.y * 64;     // 0..1472
    int isR = (nbase >= 768);
    int obase = isR ? (nbase - 768) : nbase;
    int cofs = isR ? 768 : 0;
    int tx = t & 15, ty = t >> 4;    // tx: 4-col group, ty: 2-row group

    float acc[2][4];
#pragma unroll
    for (int r = 0; r < 2; r++)
#pragma unroll
        for (int c = 0; c < 4; c++) acc[r][c] = 0.f;

    for (int k0 = 0; k0 < H_; k0 += 16) {
#pragma unroll
        for (int it = 0; it < 2; it++) {
            int q = t + it * 256;
            int row = q >> 4, kk = q & 15;
            As[kk][row] = g_yrot[(Mtile * 32 + row) * H_ + k0 + kk];
        }
#pragma unroll
        for (int it = 0; it < 4; it++) {
            int q = t + it * 256;
            int nn = q >> 4, kk = q & 15;
            Bs[kk][nn] = W1[(obase + nn) * 1536 + cofs + k0 + kk];
        }
        __syncthreads();
#pragma unroll
        for (int kk = 0; kk < 16; kk++) {
            float a0 = As[kk][ty * 2 + 0];
            float a1 = As[kk][ty * 2 + 1];
            float4 b = *(const float4*)&Bs[kk][tx * 4];
            acc[0][0] += a0 * b.x; acc[0][1] += a0 * b.y;
            acc[0][2] += a0 * b.z; acc[0][3] += a0 * b.w;
            acc[1][0] += a1 * b.x; acc[1][1] += a1 * b.y;
            acc[1][2] += a1 * b.z; acc[1][3] += a1 * b.w;
        }
        __syncthreads();
    }

    int s0 = Mtile * 32 + ty * 2;
#pragma unroll
    for (int c = 0; c < 4; c++) {
        int o = obase + tx * 4 + c;
        if (isR) {
            float bb = b1[o];
            g_R[(s0 + 0) * H_ + o] = acc[0][c] + bb;
            g_R[(s0 + 1) * H_ + o] = acc[1][c] + bb;
        } else {
            g_L[(s0 + 0) * H_ + o] = acc[0][c];
            g_L[(s0 + 1) * H_ + o] = acc[1][c];
        }
    }
}

// ---------------------------------------------------------------------------
// Fused kernel: blocks 0..399 = main GEMM tiles (R1-proven single-buffer loop),
//               blocks 400..499 = tail (output cols 256-259, rel index 64).
// ---------------------------------------------------------------------------
__global__ __launch_bounds__(256, 2) void fused_kernel(const float* __restrict__ W2,
                                                       const float* __restrict__ b2,
                                                       float* __restrict__ out) {
    __shared__ __align__(16) union SmemU {
        struct { float As[16][132]; float Bs[16][132]; } m;   // 16896 B
        struct { float W2s[4 * H_]; float Ls[3 * H_]; } tl;   // 21504 B
    } sm;

    int t = threadIdx.x;
    int bx = blockIdx.x;

    if (bx < 400) {
        // ---------------- main GEMM path (R1 structure) ----------------
        int Mtile = bx >> 1;
        int Ntile = bx & 1;
        int tx = t & 15, ty = t >> 4;

        int rowA = t >> 2;        // 0..63
        int segOff = (t & 3) * 4; // 0,4,8,12

        int p0 = Mtile * 128 + rowA;
        int p1 = p0 + 64;
        int i0 = p0 / 160, j0 = p0 - i0 * 160;
        int i1 = p1 / 160, j1 = p1 - i1 * 160;
        const float* Lp0 = g_L + i0 * H_;
        const float* Rp0 = g_R + j0 * H_;
        const float* Lp1 = g_L + i1 * H_;
        const float* Rp1 = g_R + j1 * H_;
        const float* Wp0 = W2 + (Ntile * 128 + rowA) * H_;
        const float* Wp1 = Wp0 + 64 * H_;

        u64 acc[4][8];
#pragma unroll
        for (int r = 0; r < 4; r++)
#pragma unroll
            for (int c = 0; c < 8; c++) acc[r][c] = 0ULL;

        // prefetch chunk 0
        float4 aP0 = reluadd4(*(const float4*)(Lp0 + segOff), *(const float4*)(Rp0 + segOff));
        float4 aP1 = reluadd4(*(const float4*)(Lp1 + segOff), *(const float4*)(Rp1 + segOff));
        float4 bP0 = *(const float4*)(Wp0 + segOff);
        float4 bP1 = *(const float4*)(Wp1 + segOff);

        for (int k0 = 0; k0 < H_; k0 += 16) {
            // stage current chunk to smem
            sm.m.As[segOff + 0][rowA] = aP0.x; sm.m.As[segOff + 1][rowA] = aP0.y;
            sm.m.As[segOff + 2][rowA] = aP0.z; sm.m.As[segOff + 3][rowA] = aP0.w;
            sm.m.As[segOff + 0][rowA + 64] = aP1.x; sm.m.As[segOff + 1][rowA + 64] = aP1.y;
            sm.m.As[segOff + 2][rowA + 64] = aP1.z; sm.m.As[segOff + 3][rowA + 64] = aP1.w;
            sm.m.Bs[segOff + 0][rowA] = bP0.x; sm.m.Bs[segOff + 1][rowA] = bP0.y;
            sm.m.Bs[segOff + 2][rowA] = bP0.z; sm.m.Bs[segOff + 3][rowA] = bP0.w;
            sm.m.Bs[segOff + 0][rowA + 64] = bP1.x; sm.m.Bs[segOff + 1][rowA + 64] = bP1.y;
            sm.m.Bs[segOff + 2][rowA + 64] = bP1.z; sm.m.Bs[segOff + 3][rowA + 64] = bP1.w;
            __syncthreads();

            // prefetch next chunk while computing
            int kn = k0 + 16;
            if (kn < H_) {
                aP0 = reluadd4(*(const float4*)(Lp0 + kn + segOff), *(const float4*)(Rp0 + kn + segOff));
                aP1 = reluadd4(*(const float4*)(Lp1 + kn + segOff), *(const float4*)(Rp1 + kn + segOff));
                bP0 = *(const float4*)(Wp0 + kn + segOff);
                bP1 = *(const float4*)(Wp1 + kn + segOff);
            }

#pragma unroll
            for (int kk = 0; kk < 16; kk++) {
                ulonglong2 av0 = *(const ulonglong2*)&sm.m.As[kk][ty * 8];
                ulonglong2 av1 = *(const ulonglong2*)&sm.m.As[kk][ty * 8 + 4];
                float4 bf0 = *(const float4*)&sm.m.Bs[kk][tx * 8];
                float4 bf1 = *(const float4*)&sm.m.Bs[kk][tx * 8 + 4];
                u64 a2[4] = {av0.x, av0.y, av1.x, av1.y};
                u64 bD[8];
                bD[0] = pack2(bf0.x, bf0.x); bD[1] = pack2(bf0.y, bf0.y);
                bD[2] = pack2(bf0.z, bf0.z); bD[3] = pack2(bf0.w, bf0.w);
                bD[4] = pack2(bf1.x, bf1.x); bD[5] = pack2(bf1.y, bf1.y);
                bD[6] = pack2(bf1.z, bf1.z); bD[7] = pack2(bf1.w, bf1.w);
#pragma unroll
                for (int rp = 0; rp < 4; rp++)
#pragma unroll
                    for (int c = 0; c < 8; c++)
                        fma2(acc[rp][c], a2[rp], bD[c]);
            }
            __syncthreads();
        }

        // epilogue: +b2, sigmoid, scatter into (65,160,160,4) layout
        int ob = Ntile * 128 + tx * 8;
        float bias[8];
#pragma unroll
        for (int c = 0; c < 8; c++) bias[c] = b2[ob + c];
        int rI0 = ob >> 2;

#pragma unroll
        for (int rp = 0; rp < 4; rp++) {
            float2 v[8];
#pragma unroll
            for (int c = 0; c < 8; c++) v[c] = unpack2(acc[rp][c]);
#pragma unroll
            for (int h = 0; h < 2; h++) {
                int r = ty * 8 + rp * 2 + h;
                int p = Mtile * 128 + r;
                int i = p / 160, j = p - i * 160;
                float4 o0, o1;
                o0.x = sigf((h ? v[0].y : v[0].x) + bias[0]);
                o0.y = sigf((h ? v[1].y : v[1].x) + bias[1]);
                o0.z = sigf((h ? v[2].y : v[2].x) + bias[2]);
                o0.w = sigf((h ? v[3].y : v[3].x) + bias[3]);
                o1.x = sigf((h ? v[4].y : v[4].x) + bias[4]);
                o1.y = sigf((h ? v[5].y : v[5].x) + bias[5]);
                o1.z = sigf((h ? v[6].y : v[6].x) + bias[6]);
                o1.w = sigf((h ? v[7].y : v[7].x) + bias[7]);
                *(float4*)&out[(((rI0 + 0) * 160 + i) * 160 + j) * 4] = o0;
                *(float4*)&out[(((rI0 + 1) * 160 + i) * 160 + j) * 4] = o1;
            }
        }
    } else {
        // ---------------- tail path: output cols 256..259 (rel index 64) ----
        float* W2s = sm.tl.W2s;      // 4 x 768
        float* Ls  = sm.tl.Ls;       // 3 x 768 (i spans <=3 values per 256 pairs)

        int bt = bx - 400;           // 0..99
        int p0 = bt * 256;
        int ibase = p0 / 160;

        for (int q = t; q < 4 * H_; q += 256) W2s[q] = W2[256 * H_ + q];
        for (int q = t; q < 3 * H_; q += 256) {
            int r = q / H_;
            int ri = ibase + r; if (ri > 159) ri = 159;
            Ls[q] = g_L[ri * H_ + (q - r * H_)];
        }
        __syncthreads();

        int p = p0 + t;
        int i = p / 160, j = p - i * 160;
        const float4* Rr = (const float4*)(g_R + j * H_);
        const float4* Lr = (const float4*)(Ls + (i - ibase) * H_);
        const float4* w0 = (const float4*)(W2s);
        const float4* w1 = (const float4*)(W2s + H_);
        const float4* w2 = (const float4*)(W2s + 2 * H_);
        const float4* w3 = (const float4*)(W2s + 3 * H_);

        float a0 = 0.f, a1 = 0.f, a2 = 0.f, a3 = 0.f;
#pragma unroll 4
        for (int kk = 0; kk < H_ / 4; kk++) {
            float4 l = Lr[kk];
            float4 r4 = Rr[kk];
            float4 hh = reluadd4(l, r4);
            float4 q0 = w0[kk], q1 = w1[kk], q2 = w2[kk], q3 = w3[kk];
            a0 = fmaf(hh.x, q0.x, fmaf(hh.y, q0.y, fmaf(hh.z, q0.z, fmaf(hh.w, q0.w, a0))));
            a1 = fmaf(hh.x, q1.x, fmaf(hh.y, q1.y, fmaf(hh.z, q1.z, fmaf(hh.w, q1.w, a1))));
            a2 = fmaf(hh.x, q2.x, fmaf(hh.y, q2.y, fmaf(hh.z, q2.z, fmaf(hh.w, q2.w, a2))));
            a3 = fmaf(hh.x, q3.x, fmaf(hh.y, q3.y, fmaf(hh.z, q3.z, fmaf(hh.w, q3.w, a3))));
        }
        float4 o;
        o.x = sigf(a0 + b2[256]);
        o.y = sigf(a1 + b2[257]);
        o.z = sigf(a2 + b2[258]);
        o.w = sigf(a3 + b2[259]);
        *(float4*)&out[((64 * 160 + i) * 160 + j) * 4] = o;
    }
}

// ---------------------------------------------------------------------------
extern "C" void kernel_launch(void* const* d_in, const int* in_sizes, int n_in,
                              void* d_out, int out_size) {
    const float* y  = (const float*)d_in[0];
    // d_in[1] = event_idx (unused by reference)
    const float* W1 = (const float*)d_in[2];
    const float* b1 = (const float*)d_in[3];
    const float* W2 = (const float*)d_in[4];
    const float* b2 = (const float*)d_in[5];
    float* out = (float*)d_out;

    rope_kernel<<<160, 384>>>(y);
    lr_kernel<<<dim3(5, 24), 256>>>(W1, b1);
    fused_kernel<<<500, 256>>>(W2, b2, out);
}

// round 10
// speedup vs baseline: 1.5564x; 1.5564x over previous
#include <cuda_runtime.h>

#define S_ 160
#define H_ 768

// scratch (device globals — no allocation allowed)
__device__ float g_yrot[S_ * H_];
__device__ float g_L[S_ * H_];
__device__ float g_R[S_ * H_];

typedef unsigned long long u64;

__device__ __forceinline__ void fma2(u64& d, u64 a, u64 b) {
    asm volatile("fma.rn.f32x2 %0, %1, %2, %0;" : "+l"(d) : "l"(a), "l"(b));
}
__device__ __forceinline__ u64 pack2(float x, float y) {
    u64 r; asm("mov.b64 %0, {%1, %2};" : "=l"(r) : "f"(x), "f"(y)); return r;
}
__device__ __forceinline__ float2 unpack2(u64 v) {
    float2 f; asm("mov.b64 {%0, %1}, %2;" : "=f"(f.x), "=f"(f.y) : "l"(v)); return f;
}
__device__ __forceinline__ float sigf(float x) { return 1.0f / (1.0f + __expf(-x)); }

__device__ __forceinline__ float4 reluadd4(float4 a, float4 b) {
    float4 r;
    r.x = fmaxf(a.x + b.x, 0.f);
    r.y = fmaxf(a.y + b.y, 0.f);
    r.z = fmaxf(a.z + b.z, 0.f);
    r.w = fmaxf(a.w + b.w, 0.f);
    return r;
}

// ---------------------------------------------------------------------------
// Kernel A: RoPE.  grid 160, block 384 (one thread per (2k,2k+1) pair)
// ---------------------------------------------------------------------------
__global__ void rope_kernel(const float* __restrict__ y) {
    int s = blockIdx.x;
    int k = threadIdx.x;  // 0..383
    float inv = expf(-(2.0f * (float)k / 768.0f) * 9.210340371976184f);
    float th = (float)s * inv;
    float sn, cs;
    sincosf(th, &sn, &cs);
    float y0 = y[s * H_ + 2 * k];
    float y1 = y[s * H_ + 2 * k + 1];
    g_yrot[s * H_ + 2 * k]     = y0 * cs - y1 * sn;
    g_yrot[s * H_ + 2 * k + 1] = y1 * cs + y0 * sn;
}

// ---------------------------------------------------------------------------
// Kernel B: L = yrot @ Wa^T ; R = yrot @ Wb^T + b1
// GEMM 160 x 1536 x 768.  BM=32, BN=64, BK=16.  grid (5, 24), 256 threads.
// 120 blocks ~= one full wave.  (R6-proven code.)
// ---------------------------------------------------------------------------
__global__ __launch_bounds__(256) void lr_kernel(const float* __restrict__ W1,
                                                 const float* __restrict__ b1) {
    __shared__ float As[16][34];    // [k][s-row], padded
    __shared__ float Bs[16][68];    // [k][n], padded

    int t = threadIdx.x;
    int Mtile = blockIdx.x;          // 0..4
    int nbase = blockIdx.y * 64;     // 0..1472
    int isR = (nbase >= 768);
    int obase = isR ? (nbase - 768) : nbase;
    int cofs = isR ? 768 : 0;
    int tx = t & 15, ty = t >> 4;    // tx: 4-col group, ty: 2-row group

    float acc[2][4];
#pragma unroll
    for (int r = 0; r < 2; r++)
#pragma unroll
        for (int c = 0; c < 4; c++) acc[r][c] = 0.f;

    for (int k0 = 0; k0 < H_; k0 += 16) {
#pragma unroll
        for (int it = 0; it < 2; it++) {
            int q = t + it * 256;
            int row = q >> 4, kk = q & 15;
            As[kk][row] = g_yrot[(Mtile * 32 + row) * H_ + k0 + kk];
        }
#pragma unroll
        for (int it = 0; it < 4; it++) {
            int q = t + it * 256;
            int nn = q >> 4, kk = q & 15;
            Bs[kk][nn] = W1[(obase + nn) * 1536 + cofs + k0 + kk];
        }
        __syncthreads();
#pragma unroll
        for (int kk = 0; kk < 16; kk++) {
            float a0 = As[kk][ty * 2 + 0];
            float a1 = As[kk][ty * 2 + 1];
            float4 b = *(const float4*)&Bs[kk][tx * 4];
            acc[0][0] += a0 * b.x; acc[0][1] += a0 * b.y;
            acc[0][2] += a0 * b.z; acc[0][3] += a0 * b.w;
            acc[1][0] += a1 * b.x; acc[1][1] += a1 * b.y;
            acc[1][2] += a1 * b.z; acc[1][3] += a1 * b.w;
        }
        __syncthreads();
    }

    int s0 = Mtile * 32 + ty * 2;
#pragma unroll
    for (int c = 0; c < 4; c++) {
        int o = obase + tx * 4 + c;
        if (isR) {
            float bb = b1[o];
            g_R[(s0 + 0) * H_ + o] = acc[0][c] + bb;
            g_R[(s0 + 1) * H_ + o] = acc[1][c] + bb;
        } else {
            g_L[(s0 + 0) * H_ + o] = acc[0][c];
            g_L[(s0 + 1) * H_ + o] = acc[1][c];
        }
    }
}

// ---------------------------------------------------------------------------
// Kernel C: main GEMM — R1-proven, VERBATIM (257 us, fma=50.2%).
//   out[p,o] = sigmoid(sum_h relu(L[i,h]+R[j,h])*W2[o,h] + b2[o]),
//   p=i*160+j, M=25600, N=256, K=768.  grid (200, 2), 256 thr.
// ---------------------------------------------------------------------------
__global__ __launch_bounds__(256, 2) void main_kernel(const float* __restrict__ W2,
                                                      const float* __restrict__ b2,
                                                      float* __restrict__ out) {
    __shared__ __align__(16) float As[16][132];  // [k][pair-row]
    __shared__ __align__(16) float Bs[16][132];  // [k][o-col]

    int t = threadIdx.x;
    int Mtile = blockIdx.x;   // 0..199
    int Ntile = blockIdx.y;   // 0..1
    int tx = t & 15, ty = t >> 4;

    int rowA = t >> 2;        // 0..63
    int seg = t & 3;
    int segOff = seg * 4;

    int p0 = Mtile * 128 + rowA;
    int p1 = p0 + 64;
    int i0 = p0 / 160, j0 = p0 - i0 * 160;
    int i1 = p1 / 160, j1 = p1 - i1 * 160;
    const float* Lp0 = g_L + i0 * H_;
    const float* Rp0 = g_R + j0 * H_;
    const float* Lp1 = g_L + i1 * H_;
    const float* Rp1 = g_R + j1 * H_;
    const float* Wp0 = W2 + (Ntile * 128 + rowA) * H_;
    const float* Wp1 = Wp0 + 64 * H_;

    u64 acc[4][8];
#pragma unroll
    for (int r = 0; r < 4; r++)
#pragma unroll
        for (int c = 0; c < 8; c++) acc[r][c] = 0ULL;

    // prefetch chunk 0
    float4 aP0 = reluadd4(*(const float4*)(Lp0 + segOff), *(const float4*)(Rp0 + segOff));
    float4 aP1 = reluadd4(*(const float4*)(Lp1 + segOff), *(const float4*)(Rp1 + segOff));
    float4 bP0 = *(const float4*)(Wp0 + segOff);
    float4 bP1 = *(const float4*)(Wp1 + segOff);

    for (int k0 = 0; k0 < H_; k0 += 16) {
        // stage current chunk to smem
        As[segOff + 0][rowA] = aP0.x; As[segOff + 1][rowA] = aP0.y;
        As[segOff + 2][rowA] = aP0.z; As[segOff + 3][rowA] = aP0.w;
        As[segOff + 0][rowA + 64] = aP1.x; As[segOff + 1][rowA + 64] = aP1.y;
        As[segOff + 2][rowA + 64] = aP1.z; As[segOff + 3][rowA + 64] = aP1.w;
        Bs[segOff + 0][rowA] = bP0.x; Bs[segOff + 1][rowA] = bP0.y;
        Bs[segOff + 2][rowA] = bP0.z; Bs[segOff + 3][rowA] = bP0.w;
        Bs[segOff + 0][rowA + 64] = bP1.x; Bs[segOff + 1][rowA + 64] = bP1.y;
        Bs[segOff + 2][rowA + 64] = bP1.z; Bs[segOff + 3][rowA + 64] = bP1.w;
        __syncthreads();

        // prefetch next chunk while computing
        int kn = k0 + 16;
        if (kn < H_) {
            aP0 = reluadd4(*(const float4*)(Lp0 + kn + segOff), *(const float4*)(Rp0 + kn + segOff));
            aP1 = reluadd4(*(const float4*)(Lp1 + kn + segOff), *(const float4*)(Rp1 + kn + segOff));
            bP0 = *(const float4*)(Wp0 + kn + segOff);
            bP1 = *(const float4*)(Wp1 + kn + segOff);
        }

#pragma unroll
        for (int kk = 0; kk < 16; kk++) {
            ulonglong2 av0 = *(const ulonglong2*)&As[kk][ty * 8];
            ulonglong2 av1 = *(const ulonglong2*)&As[kk][ty * 8 + 4];
            float4 bf0 = *(const float4*)&Bs[kk][tx * 8];
            float4 bf1 = *(const float4*)&Bs[kk][tx * 8 + 4];
            u64 a2[4] = {av0.x, av0.y, av1.x, av1.y};
            u64 bD[8];
            bD[0] = pack2(bf0.x, bf0.x); bD[1] = pack2(bf0.y, bf0.y);
            bD[2] = pack2(bf0.z, bf0.z); bD[3] = pack2(bf0.w, bf0.w);
            bD[4] = pack2(bf1.x, bf1.x); bD[5] = pack2(bf1.y, bf1.y);
            bD[6] = pack2(bf1.z, bf1.z); bD[7] = pack2(bf1.w, bf1.w);
#pragma unroll
            for (int rp = 0; rp < 4; rp++)
#pragma unroll
                for (int c = 0; c < 8; c++)
                    fma2(acc[rp][c], a2[rp], bD[c]);
        }
        __syncthreads();
    }

    // epilogue: +b2, sigmoid, scatter into (65,160,160,4) layout
    int ob = Ntile * 128 + tx * 8;   // multiple of 8 -> o%4 == c%4
    float bias[8];
#pragma unroll
    for (int c = 0; c < 8; c++) bias[c] = b2[ob + c];
    int rI0 = ob >> 2;               // rel index for cols 0..3; +1 for 4..7

#pragma unroll
    for (int rp = 0; rp < 4; rp++) {
        float2 v[8];
#pragma unroll
        for (int c = 0; c < 8; c++) v[c] = unpack2(acc[rp][c]);
#pragma unroll
        for (int h = 0; h < 2; h++) {
            int r = ty * 8 + rp * 2 + h;
            int p = Mtile * 128 + r;
            int i = p / 160, j = p - i * 160;
            float4 o0, o1;
            o0.x = sigf((h ? v[0].y : v[0].x) + bias[0]);
            o0.y = sigf((h ? v[1].y : v[1].x) + bias[1]);
            o0.z = sigf((h ? v[2].y : v[2].x) + bias[2]);
            o0.w = sigf((h ? v[3].y : v[3].x) + bias[3]);
            o1.x = sigf((h ? v[4].y : v[4].x) + bias[4]);
            o1.y = sigf((h ? v[5].y : v[5].x) + bias[5]);
            o1.z = sigf((h ? v[6].y : v[6].x) + bias[6]);
            o1.w = sigf((h ? v[7].y : v[7].x) + bias[7]);
            *(float4*)&out[(((rI0 + 0) * 160 + i) * 160 + j) * 4] = o0;
            *(float4*)&out[(((rI0 + 1) * 160 + i) * 160 + j) * 4] = o1;
        }
    }
}

// ---------------------------------------------------------------------------
// Kernel D: tail outputs o = 256..259 (rel index 64).  Standalone version of
// the R6/R8-proven one-pair-per-thread path.  grid 100, block 256.
// ---------------------------------------------------------------------------
__global__ __launch_bounds__(256) void tail_kernel(const float* __restrict__ W2,
                                                   const float* __restrict__ b2,
                                                   float* __restrict__ out) {
    __shared__ float W2s[4 * H_];   // 12288 B
    __shared__ float Ls[3 * H_];    // 9216 B  (i spans <=3 values per 256 pairs)

    int t = threadIdx.x;
    int bt = blockIdx.x;             // 0..99
    int p0 = bt * 256;
    int ibase = p0 / 160;

    for (int q = t; q < 4 * H_; q += 256) W2s[q] = W2[256 * H_ + q];
    for (int q = t; q < 3 * H_; q += 256) {
        int r = q / H_;
        int ri = ibase + r; if (ri > 159) ri = 159;
        Ls[q] = g_L[ri * H_ + (q - r * H_)];
    }
    __syncthreads();

    int p = p0 + t;
    int i = p / 160, j = p - i * 160;
    const float4* Rr = (const float4*)(g_R + j * H_);
    const float4* Lr = (const float4*)(Ls + (i - ibase) * H_);
    const float4* w0 = (const float4*)(W2s);
    const float4* w1 = (const float4*)(W2s + H_);
    const float4* w2 = (const float4*)(W2s + 2 * H_);
    const float4* w3 = (const float4*)(W2s + 3 * H_);

    float a0 = 0.f, a1 = 0.f, a2 = 0.f, a3 = 0.f;
#pragma unroll 4
    for (int kk = 0; kk < H_ / 4; kk++) {
        float4 l = Lr[kk];
        float4 r4 = Rr[kk];
        float4 hh = reluadd4(l, r4);
        float4 q0 = w0[kk], q1 = w1[kk], q2 = w2[kk], q3 = w3[kk];
        a0 = fmaf(hh.x, q0.x, fmaf(hh.y, q0.y, fmaf(hh.z, q0.z, fmaf(hh.w, q0.w, a0))));
        a1 = fmaf(hh.x, q1.x, fmaf(hh.y, q1.y, fmaf(hh.z, q1.z, fmaf(hh.w, q1.w, a1))));
        a2 = fmaf(hh.x, q2.x, fmaf(hh.y, q2.y, fmaf(hh.z, q2.z, fmaf(hh.w, q2.w, a2))));
        a3 = fmaf(hh.x, q3.x, fmaf(hh.y, q3.y, fmaf(hh.z, q3.z, fmaf(hh.w, q3.w, a3))));
    }
    float4 o;
    o.x = sigf(a0 + b2[256]);
    o.y = sigf(a1 + b2[257]);
    o.z = sigf(a2 + b2[258]);
    o.w = sigf(a3 + b2[259]);
    *(float4*)&out[((64 * 160 + i) * 160 + j) * 4] = o;
}

// ---------------------------------------------------------------------------
extern "C" void kernel_launch(void* const* d_in, const int* in_sizes, int n_in,
                              void* d_out, int out_size) {
    const float* y  = (const float*)d_in[0];
    // d_in[1] = event_idx (unused by reference)
    const float* W1 = (const float*)d_in[2];
    const float* b1 = (const float*)d_in[3];
    const float* W2 = (const float*)d_in[4];
    const float* b2 = (const float*)d_in[5];
    float* out = (float*)d_out;

    rope_kernel<<<160, 384>>>(y);
    lr_kernel<<<dim3(5, 24), 256>>>(W1, b1);
    tail_kernel<<<100, 256>>>(W2, b2, out);
    main_kernel<<<dim3(200, 2), 256>>>(W2, b2, out);
}